// round 12
// baseline (speedup 1.0000x reference)
#include <cuda_runtime.h>
#include <cstdint>

#define BB   8
#define LL   4096
#define KNN  16
#define DD   128

// scratch for neighbor indices (no cudaMalloc allowed)
__device__ int g_nbr[BB * LL * KNN];

// ---------------------------------------------------------------------------
// Kernel 1: warp-cooperative exact top-16 KNN + euclidian output.
// One WARP per query; sorted top-16 distributed across lanes 0..15.
// Block = 512 threads (16 queries) with 48KB smem -> 2048 threads/SM resident.
// ---------------------------------------------------------------------------
__global__ __launch_bounds__(512)
void knn_kernel(const float* __restrict__ frame, float* __restrict__ out_euclid)
{
    __shared__ float sx[LL];
    __shared__ float sy[LL];
    __shared__ float sz[LL];

    const int b     = blockIdx.y;
    const int lane  = threadIdx.x & 31;
    const int wib   = threadIdx.x >> 5;            // warp in block: 0..15
    const int q     = blockIdx.x * 16 + wib;       // gridDim.x = 256
    const float* fb = frame + (size_t)b * LL * 12;

    // stage centers: frame[b, j, 0, 0..2] (float4 load, drop .w)
    for (int j = threadIdx.x; j < LL; j += 512) {
        const float4 v = *reinterpret_cast<const float4*>(fb + j * 12);
        sx[j] = v.x;
        sy[j] = v.y;
        sz[j] = v.z;
    }
    __syncthreads();

    const float qx = sx[q], qy = sy[q], qz = sz[q];

    const unsigned FULL = 0xffffffffu;
    const float INF = __int_as_float(0x7f800000);

    // distributed top-16: lanes 0..15 hold the sorted list; lanes 16..31
    // permanently hold +inf so insertion-position ballots are well-formed.
    float lk  = INF;   // key (distance)
    int   li  = -1;    // neighbor index
    float thr = INF;   // current 16th-best distance (lane 15's key)

    // insert all candidates flagged in `mask` (lane s holds distance `dist`,
    // global index jbase+s), ascending lane order == ascending j order.
    // strict '<' everywhere => jax.lax.top_k stable tie semantics.
    auto insert_all = [&](unsigned mask, float dist, int jbase) {
        while (mask) {
            const int   s  = __ffs(mask) - 1;
            const float cd = __shfl_sync(FULL, dist, s);
            const int   ci = jbase + s;

            const float up_d = __shfl_up_sync(FULL, lk, 1);
            const int   up_i = __shfl_up_sync(FULL, li, 1);
            const unsigned posb = __ballot_sync(FULL, cd < lk);
            const int p = __ffs(posb) - 1;      // insertion position (<=15)

            if (lane < 16) {
                if (lane == p)      { lk = cd;   li = ci;   }
                else if (lane > p)  { lk = up_d; li = up_i; }
            }
            thr = __shfl_sync(FULL, lk, 15);

            mask &= ~(1u << s);
            mask &= __ballot_sync(FULL, dist < thr);
        }
    };

    for (int j0 = 0; j0 < LL; j0 += 64) {
        const int jA = j0 + lane;
        const int jB = j0 + 32 + lane;

        const float axd = qx - sx[jA];
        const float ayd = qy - sy[jA];
        const float azd = qz - sz[jA];
        const float bxd = qx - sx[jB];
        const float byd = qy - sy[jB];
        const float bzd = qz - sz[jB];
        const float dA = fmaf(azd, azd, fmaf(ayd, ayd, axd * axd));
        const float dB = fmaf(bzd, bzd, fmaf(byd, byd, bxd * bxd));

        const unsigned mA = __ballot_sync(FULL, dA < thr);
        if (mA) insert_all(mA, dA, j0);
        const unsigned mB = __ballot_sync(FULL, dB < thr);
        if (mB) insert_all(mB, dB, j0 + 32);
    }

    // epilogue: lanes 0..15 each own one neighbor
    if (lane < KNN) {
        const int nb = li;
        const size_t base = ((size_t)b * LL + q) * KNN;
        g_nbr[base + lane] = nb;

        const float dx = sx[nb] - qx;
        const float dy = sy[nb] - qy;
        const float dz = sz[nb] - qz;

        const float* fq = fb + q * 12;   // rotation rows, broadcast across lanes
        const float e0 = fmaf(dz, fq[9],  fmaf(dy, fq[6], dx * fq[3]));
        const float e1 = fmaf(dz, fq[10], fmaf(dy, fq[7], dx * fq[4]));
        const float e2 = fmaf(dz, fq[11], fmaf(dy, fq[8], dx * fq[5]));

        float* o = out_euclid + (base + lane) * 3;
        o[0] = e0; o[1] = e1; o[2] = e2;
    }
}

// ---------------------------------------------------------------------------
// Kernel 2: gather attr rows. One warp per TWO (b,l,k) rows; lane i copies
// float4 i of each row (2 independent LDG.128/STG.128 per lane for MLP).
// ---------------------------------------------------------------------------
__global__ __launch_bounds__(256)
void gather_kernel(const float* __restrict__ attr, float* __restrict__ out_attr)
{
    const int warp = (blockIdx.x * blockDim.x + threadIdx.x) >> 5;
    const int lane = threadIdx.x & 31;
    const int row0 = warp * 2;
    if (row0 >= BB * LL * KNN) return;

    const int b = row0 / (LL * KNN);           // rows row0, row0+1 share b
    const int2 jj = *reinterpret_cast<const int2*>(g_nbr + row0);

    const float4* s0 = reinterpret_cast<const float4*>(attr + ((size_t)b * LL + jj.x) * DD);
    const float4* s1 = reinterpret_cast<const float4*>(attr + ((size_t)b * LL + jj.y) * DD);
    float4* d0 = reinterpret_cast<float4*>(out_attr + (size_t)row0 * DD);
    float4* d1 = d0 + DD / 4;

    const float4 v0 = s0[lane];
    const float4 v1 = s1[lane];
    d0[lane] = v0;
    d1[lane] = v1;
}

extern "C" void kernel_launch(void* const* d_in, const int* in_sizes, int n_in,
                              void* d_out, int out_size)
{
    const float* frame = (const float*)d_in[0];
    const float* attr  = (const float*)d_in[1];
    if (n_in >= 2 && in_sizes[0] == BB * LL * DD) {   // defensive order check
        attr  = (const float*)d_in[0];
        frame = (const float*)d_in[1];
    }

    float* out        = (float*)d_out;
    float* out_euclid = out;                               // B*L*K*3
    float* out_attr   = out + (size_t)BB * LL * KNN * 3;   // B*L*K*D

    knn_kernel<<<dim3(LL / 16, BB), 512>>>(frame, out_euclid);

    const int rows = BB * LL * KNN;                        // 524288 rows
    gather_kernel<<<rows / 16, 256>>>(attr, out_attr);     // 2 rows per warp
}

// round 13
// speedup vs baseline: 1.3209x; 1.3209x over previous
#include <cuda_runtime.h>
#include <cstdint>

#define BB   8
#define LL   4096
#define KNN  16
#define DD   128
#define NGRP 128          // groups of 32 per batch
#define NBIN 4096         // 16^3 morton bins

typedef unsigned long long u64;
typedef unsigned int       u32;

// scratch (no cudaMalloc allowed)
__device__ float4 g_pts [BB * LL];     // sorted points: x,y,z, idx-bits in w
__device__ float4 g_hdr [BB * NGRP];   // group bounding sphere: cx,cy,cz,r
__device__ int    g_spos[BB * LL];     // orig idx -> sorted pos
__device__ int    g_nbr [BB * LL * KNN];

__device__ __forceinline__ u32 spread4(int v) {
    u32 x = (u32)v;
    return (x & 1u) | ((x & 2u) << 2) | ((x & 4u) << 4) | ((x & 8u) << 6);
}

// ---------------------------------------------------------------------------
// Kernel A: counting sort by 12-bit Morton code. One block per batch.
// ---------------------------------------------------------------------------
__global__ __launch_bounds__(1024)
void sort_kernel(const float* __restrict__ frame)
{
    __shared__ u32 bins[NBIN];
    __shared__ u32 wpart[32];
    const int b    = blockIdx.x;
    const int t    = threadIdx.x;
    const int lane = t & 31;
    const int wid  = t >> 5;
    const float* fb = frame + (size_t)b * LL * 12;
    const u32 FULL = 0xffffffffu;

    for (int i = t; i < NBIN; i += 1024) bins[i] = 0;
    __syncthreads();

    u32 code[4];
#pragma unroll
    for (int k = 0; k < 4; k++) {
        const int j = k * 1024 + t;
        const float4 v = *reinterpret_cast<const float4*>(fb + j * 12);
        const int ix = min(15, max(0, (int)floorf((v.x + 4.0f) * 2.0f)));
        const int iy = min(15, max(0, (int)floorf((v.y + 4.0f) * 2.0f)));
        const int iz = min(15, max(0, (int)floorf((v.z + 4.0f) * 2.0f)));
        code[k] = spread4(ix) | (spread4(iy) << 1) | (spread4(iz) << 2);
        atomicAdd(&bins[code[k]], 1u);
    }
    __syncthreads();

    // exclusive scan over 4096 bins (thread t owns bins 4t..4t+3)
    const u32 c0 = bins[t*4+0], c1 = bins[t*4+1], c2 = bins[t*4+2], c3 = bins[t*4+3];
    const u32 tot = c0 + c1 + c2 + c3;
    u32 x = tot;
#pragma unroll
    for (int o = 1; o < 32; o <<= 1) {
        const u32 y = __shfl_up_sync(FULL, x, o);
        if (lane >= o) x += y;
    }
    if (lane == 31) wpart[wid] = x;
    __syncthreads();
    if (wid == 0) {
        const u32 w = wpart[lane];
        u32 xi = w;
#pragma unroll
        for (int o = 1; o < 32; o <<= 1) {
            const u32 y = __shfl_up_sync(FULL, xi, o);
            if (lane >= o) xi += y;
        }
        wpart[lane] = xi - w;      // exclusive warp base
    }
    __syncthreads();
    const u32 base = wpart[wid] + x - tot;
    bins[t*4+0] = base;
    bins[t*4+1] = base + c0;
    bins[t*4+2] = base + c0 + c1;
    bins[t*4+3] = base + c0 + c1 + c2;
    __syncthreads();

    // scatter (bins now act as cursors)
#pragma unroll
    for (int k = 0; k < 4; k++) {
        const int j = k * 1024 + t;
        const float4 v = *reinterpret_cast<const float4*>(fb + j * 12);
        const u32 pos = atomicAdd(&bins[code[k]], 1u);
        g_pts[b * LL + pos] = make_float4(v.x, v.y, v.z, __int_as_float(j));
        g_spos[b * LL + j]  = (int)pos;
    }
}

// ---------------------------------------------------------------------------
// Kernel B: group bounding spheres (conservative). One warp per group.
// ---------------------------------------------------------------------------
__global__ __launch_bounds__(256)
void hdr_kernel()
{
    const int w    = (blockIdx.x * 256 + threadIdx.x) >> 5;   // 0..BB*NGRP-1
    const int lane = threadIdx.x & 31;
    const int b = w >> 7;
    const int g = w & (NGRP - 1);
    const u32 FULL = 0xffffffffu;

    const float4 p = g_pts[b * LL + g * 32 + lane];
    float cx = p.x, cy = p.y, cz = p.z;
#pragma unroll
    for (int o = 16; o; o >>= 1) {
        cx += __shfl_xor_sync(FULL, cx, o);
        cy += __shfl_xor_sync(FULL, cy, o);
        cz += __shfl_xor_sync(FULL, cz, o);
    }
    cx *= 0.03125f; cy *= 0.03125f; cz *= 0.03125f;

    const float dx = p.x - cx, dy = p.y - cy, dz = p.z - cz;
    float d2 = fmaf(dz, dz, fmaf(dy, dy, dx * dx));
#pragma unroll
    for (int o = 16; o; o >>= 1)
        d2 = fmaxf(d2, __shfl_xor_sync(FULL, d2, o));

    if (lane == 0)
        g_hdr[b * NGRP + g] =
            make_float4(cx, cy, cz, __fsqrt_rn(d2) * 1.0001f + 1e-7f);
}

// ---------------------------------------------------------------------------
// Kernel C: exact KNN. One warp per query; top-16 as u64 keys
// (dist_bits<<32 | idx) distributed over lanes 0..15 sorted ascending.
// ---------------------------------------------------------------------------
__global__ __launch_bounds__(256)
void knn_kernel(const float* __restrict__ frame, float* __restrict__ out_euclid)
{
    __shared__ float4 shdr[NGRP];
    const int b    = blockIdx.y;
    const int lane = threadIdx.x & 31;
    const int wib  = threadIdx.x >> 5;
    const int q    = blockIdx.x * 8 + wib;        // gridDim.x = 512
    const float* fb = frame + (size_t)b * LL * 12;
    const float4* pts = g_pts + b * LL;
    const u32 FULL = 0xffffffffu;

    if (threadIdx.x < NGRP) shdr[threadIdx.x] = g_hdr[b * NGRP + threadIdx.x];
    __syncthreads();

    const float4 qv = *reinterpret_cast<const float4*>(fb + q * 12);

    // --- own group: compute keys and bitonic-sort 32 ascending ---
    const int g0 = g_spos[b * LL + q] >> 5;
    u64 lk;
    {
        const float4 p = pts[g0 * 32 + lane];
        const float dx = qv.x - p.x, dy = qv.y - p.y, dz = qv.z - p.z;
        const float d  = fmaf(dz, dz, fmaf(dy, dy, dx * dx));
        lk = ((u64)__float_as_uint(d) << 32) | (u32)__float_as_int(p.w);
#pragma unroll
        for (int k = 2; k <= 32; k <<= 1) {
#pragma unroll
            for (int j = k >> 1; j > 0; j >>= 1) {
                const u64 other = __shfl_xor_sync(FULL, lk, j);
                const bool take_min = (((lane & k) == 0) == ((lane & j) == 0));
                if (take_min ? (other < lk) : (other > lk)) lk = other;
            }
        }
        if (lane >= 16) lk = ~0ull;   // sentinel: insertion pos always defined
    }

    u64   thrk  = __shfl_sync(FULL, lk, 15);
    float thr_d = __uint_as_float((u32)(thrk >> 32));
    float srad  = __fsqrt_rn(thr_d) * 1.00001f + 1e-9f;

    // --- prefilter all 128 group bounds (lane-parallel) ---
    u32 surv[4];
#pragma unroll
    for (int r = 0; r < 4; r++) {
        const float4 h = shdr[r * 32 + lane];
        const float dx = qv.x - h.x, dy = qv.y - h.y, dz = qv.z - h.z;
        const float d2 = fmaf(dz, dz, fmaf(dy, dy, dx * dx));
        const float rhs = h.w + srad;
        surv[r] = __ballot_sync(FULL, d2 <= fmaf(rhs, rhs, 1e-5f * rhs * rhs + 1e-12f));
    }
    surv[g0 >> 5] &= ~(1u << (g0 & 31));   // own group already done

    // --- scan surviving groups ---
#pragma unroll
    for (int r = 0; r < 4; r++) {
        u32 m = surv[r];
        while (m) {
            const int c = r * 32 + (__ffs(m) - 1);
            m &= m - 1;

            // recheck against tightened threshold (warp-uniform)
            const float4 h = shdr[c];
            {
                const float dx = qv.x - h.x, dy = qv.y - h.y, dz = qv.z - h.z;
                const float d2 = fmaf(dz, dz, fmaf(dy, dy, dx * dx));
                const float rhs = h.w + srad;
                if (d2 > fmaf(rhs, rhs, 1e-5f * rhs * rhs + 1e-12f)) continue;
            }

            const float4 p = pts[c * 32 + lane];
            const float dx = qv.x - p.x, dy = qv.y - p.y, dz = qv.z - p.z;
            const float d  = fmaf(dz, dz, fmaf(dy, dy, dx * dx));
            const u64 key  = ((u64)__float_as_uint(d) << 32) | (u32)__float_as_int(p.w);

            u32 mask = __ballot_sync(FULL, key < thrk);
            if (!mask) continue;
            do {
                const int sl = __ffs(mask) - 1;
                mask &= mask - 1;
                const u64 ck   = __shfl_sync(FULL, key, sl);
                const u32 posb = __ballot_sync(FULL, ck < lk);   // bits >=16 always set
                const int pp   = __ffs(posb) - 1;
                const u64 up   = __shfl_up_sync(FULL, lk, 1);
                if (lane < 16 && lane >= pp) lk = (lane == pp) ? ck : up;
            } while (mask);
            thrk  = __shfl_sync(FULL, lk, 15);
            thr_d = __uint_as_float((u32)(thrk >> 32));
            srad  = __fsqrt_rn(thr_d) * 1.00001f + 1e-9f;
        }
    }

    // --- epilogue: lanes 0..15 own neighbors in exact stable order ---
    if (lane < KNN) {
        const int nb = (int)(u32)(lk & 0xffffffffu);
        const size_t base = ((size_t)b * LL + q) * KNN;
        g_nbr[base + lane] = nb;

        const float4 nv = *reinterpret_cast<const float4*>(fb + nb * 12);
        const float dx = nv.x - qv.x, dy = nv.y - qv.y, dz = nv.z - qv.z;

        const float* fq = fb + q * 12;
        const float e0 = fmaf(dz, fq[9],  fmaf(dy, fq[6], dx * fq[3]));
        const float e1 = fmaf(dz, fq[10], fmaf(dy, fq[7], dx * fq[4]));
        const float e2 = fmaf(dz, fq[11], fmaf(dy, fq[8], dx * fq[5]));

        float* o = out_euclid + (base + lane) * 3;
        o[0] = e0; o[1] = e1; o[2] = e2;
    }
}

// ---------------------------------------------------------------------------
// Kernel D: gather attr rows. One warp per FOUR rows (4x float4 MLP per lane).
// ---------------------------------------------------------------------------
__global__ __launch_bounds__(256)
void gather_kernel(const float* __restrict__ attr, float* __restrict__ out_attr)
{
    const int warp = (blockIdx.x * 256 + threadIdx.x) >> 5;
    const int lane = threadIdx.x & 31;
    const int row0 = warp * 4;
    if (row0 >= BB * LL * KNN) return;

    const int b = row0 / (LL * KNN);
    const int4 jj = *reinterpret_cast<const int4*>(g_nbr + row0);
    const float* ab = attr + (size_t)b * LL * DD;

    const float4 v0 = reinterpret_cast<const float4*>(ab + (size_t)jj.x * DD)[lane];
    const float4 v1 = reinterpret_cast<const float4*>(ab + (size_t)jj.y * DD)[lane];
    const float4 v2 = reinterpret_cast<const float4*>(ab + (size_t)jj.z * DD)[lane];
    const float4 v3 = reinterpret_cast<const float4*>(ab + (size_t)jj.w * DD)[lane];

    float4* d = reinterpret_cast<float4*>(out_attr + (size_t)row0 * DD);
    d[lane]      = v0;
    d[32 + lane] = v1;
    d[64 + lane] = v2;
    d[96 + lane] = v3;
}

extern "C" void kernel_launch(void* const* d_in, const int* in_sizes, int n_in,
                              void* d_out, int out_size)
{
    const float* frame = (const float*)d_in[0];
    const float* attr  = (const float*)d_in[1];
    if (n_in >= 2 && in_sizes[0] == BB * LL * DD) {   // defensive order check
        attr  = (const float*)d_in[0];
        frame = (const float*)d_in[1];
    }

    float* out        = (float*)d_out;
    float* out_euclid = out;                               // B*L*K*3
    float* out_attr   = out + (size_t)BB * LL * KNN * 3;   // B*L*K*D

    sort_kernel<<<BB, 1024>>>(frame);
    hdr_kernel<<<BB * NGRP / 8, 256>>>();
    knn_kernel<<<dim3(LL / 8, BB), 256>>>(frame, out_euclid);

    const int rows = BB * LL * KNN;                        // 524288 rows
    gather_kernel<<<rows / 32, 256>>>(attr, out_attr);     // 4 rows per warp
}